// round 9
// baseline (speedup 1.0000x reference)
#include <cuda_runtime.h>
#include <cuda_bf16.h>
#include <cstdint>

#define NN 50000
#define EE 400000
#define TT 3
#define KD 256
#define HH 8
#define HD 32
#define CAP 64   // max in-degree bucket (Poisson(8): max~26, huge margin)

// ---- scratch (device globals; no allocs allowed) ----
__device__ float g_h[TT * NN * KD];      // per-type transformed features
__device__ float g_sl[TT * NN * HH];
__device__ float g_sr[TT * NN * HH];
__device__ int   g_cnt[TT * NN];
__device__ int   g_adj[TT * NN * CAP];
__device__ __nv_bfloat16 g_xh[NN * KD];          // x hi plane
__device__ __nv_bfloat16 g_xl[NN * KD];          // x lo plane
__device__ __nv_bfloat16 g_Wh[TT * KD * KD];     // W^T hi plane  [t][n][k]
__device__ __nv_bfloat16 g_Wl[TT * KD * KD];     // W^T lo plane

static __device__ __forceinline__ uint32_t s2u(const void* p) {
    uint32_t a;
    asm("{ .reg .u64 t; cvta.to.shared.u64 t, %1; cvt.u32.u64 %0, t; }" : "=r"(a) : "l"(p));
    return a;
}
static __device__ __forceinline__ void cp16(uint32_t dst, const void* src, int sz) {
    asm volatile("cp.async.cg.shared.global [%0], [%1], 16, %2;"
                 :: "r"(dst), "l"(src), "r"(sz) : "memory");
}
static __device__ __forceinline__ void mma16(float* c, const uint32_t* a,
                                             uint32_t b0, uint32_t b1) {
    asm volatile(
        "mma.sync.aligned.m16n8k16.row.col.f32.bf16.bf16.f32 "
        "{%0,%1,%2,%3},{%4,%5,%6,%7},{%8,%9},{%0,%1,%2,%3};"
        : "+f"(c[0]), "+f"(c[1]), "+f"(c[2]), "+f"(c[3])
        : "r"(a[0]), "r"(a[1]), "r"(a[2]), "r"(a[3]), "r"(b0), "r"(b1));
}

// ---------------- prep: zero counters ----------------
__global__ void zero_cnt_kernel() {
    int i = blockIdx.x * blockDim.x + threadIdx.x;
    if (i < TT * NN) g_cnt[i] = 0;
}

// ---------------- prep: bucketed CSR build ----------------
__global__ void build_kernel(const int* __restrict__ ei) {
    int i = blockIdx.x * blockDim.x + threadIdx.x;
    if (i >= TT * EE) return;
    int t = i / EE, e = i - t * EE;
    int s = ei[t * 2 * EE + e];
    int d = ei[t * 2 * EE + EE + e];
    int pos = atomicAdd(&g_cnt[t * NN + d], 1);
    if (pos < CAP) g_adj[(t * NN + d) * CAP + pos] = s;
}

// ---------------- prep: split-bf16 planes ----------------
__global__ void split_x_kernel(const float* __restrict__ x) {
    int i = blockIdx.x * blockDim.x + threadIdx.x;
    if (i >= NN * KD) return;
    float v = x[i];
    __nv_bfloat16 h = __float2bfloat16(v);
    g_xh[i] = h;
    g_xl[i] = __float2bfloat16(v - __bfloat162float(h));
}
// W[t][k][n] -> planes [t][n][k]  (reads coalesced: n fastest)
__global__ void split_W_kernel(const float* __restrict__ W) {
    int i = blockIdx.x * blockDim.x + threadIdx.x;
    if (i >= TT * KD * KD) return;
    int n = i & 255, k = (i >> 8) & 255, t = i >> 16;
    float v = W[i];
    __nv_bfloat16 h = __float2bfloat16(v);
    int o = (t << 16) + (n << 8) + k;
    g_Wh[o] = h;
    g_Wl[o] = __float2bfloat16(v - __bfloat162float(h));
}

// ---------------- split-bf16 mma.sync GEMM + fused score epilogue ----------------
// CTA 128x128xK256, BK=16, 8 warps 2x4, warp tile 64x32.
// 4-stage cp.async ring, ONE __syncthreads per iteration (write target at iter kt
// is the buffer whose readers finished at iter kt-1; the start-of-iter sync covers
// both data-visibility and WAR). Tail keeps wait_group invariant via empty commits.
#define ROW_W 12                      // words per row
#define PLANE_W (128 * ROW_W)         // 1536 words per plane
#define BUF_W (4 * PLANE_W)           // 6144 words per stage
#define STAGES 4
#define SM_TOTAL (STAGES * BUF_W * 4) // 98304 B

__global__ void __launch_bounds__(256, 2) gemm_scores_kernel(const float* __restrict__ a_l,
                                                             const float* __restrict__ a_r) {
    extern __shared__ char smraw[];
    uint32_t* smw = (uint32_t*)smraw;
    const uint32_t sbase = s2u(smraw);

    const int tid = threadIdx.x;
    const int wid = tid >> 5, lane = tid & 31;
    const int g = lane >> 2, tg = lane & 3;
    const int wr = wid >> 2, wc = wid & 3;
    const int t = blockIdx.z;
    const int m0 = blockIdx.x * 128, n0 = blockIdx.y * 128;

    float acc[4][4][4];
#pragma unroll
    for (int i = 0; i < 4; i++)
#pragma unroll
        for (int j = 0; j < 4; j++)
#pragma unroll
            for (int q = 0; q < 4; q++) acc[i][j][q] = 0.f;

    const int lr = tid >> 1, half = tid & 1;     // load row / 16B-half
    const int gr = m0 + lr;                       // A global row
    const int nr = n0 + lr;                       // B global row (n index)

    auto loadTile = [&](int kt, int buf) {
        const int k0 = kt * 16;
        uint32_t sb = sbase + (uint32_t)buf * BUF_W * 4;
        uint32_t wo = (uint32_t)(lr * ROW_W + half * 4) * 4;
        int asz = gr < NN ? 16 : 0;
        cp16(sb + wo, g_xh + (size_t)gr * KD + k0 + half * 8, asz);
        cp16(sb + PLANE_W * 4 + wo, g_xl + (size_t)gr * KD + k0 + half * 8, asz);
        size_t woff = ((size_t)t * KD + nr) * KD + k0 + half * 8;
        cp16(sb + 2 * PLANE_W * 4 + wo, g_Wh + woff, 16);
        cp16(sb + 3 * PLANE_W * 4 + wo, g_Wl + woff, 16);
        asm volatile("cp.async.commit_group;" ::: "memory");
    };

    loadTile(0, 0);
    loadTile(1, 1);
    loadTile(2, 2);

    for (int kt = 0; kt < 16; kt++) {
        const int buf = kt & 3;
        // invariant: 3 groups outstanding at this point -> wait until <=2 => group kt done
        asm volatile("cp.async.wait_group 2;" ::: "memory");
        __syncthreads();
        if (kt + 3 < 16) loadTile(kt + 3, (kt + 3) & 3);
        else             asm volatile("cp.async.commit_group;" ::: "memory");  // empty group

        const uint32_t* Ah = smw + buf * BUF_W;
        const uint32_t* Al = Ah + PLANE_W;
        const uint32_t* Bh = Ah + 2 * PLANE_W;
        const uint32_t* Bl = Ah + 3 * PLANE_W;

        uint32_t ah[4][4], al[4][4];
#pragma unroll
        for (int mf = 0; mf < 4; mf++) {
            int w0 = (wr * 64 + mf * 16 + g) * ROW_W + tg;
            int w1 = w0 + 8 * ROW_W;
            ah[mf][0] = Ah[w0]; ah[mf][1] = Ah[w1];
            ah[mf][2] = Ah[w0 + 4]; ah[mf][3] = Ah[w1 + 4];
            al[mf][0] = Al[w0]; al[mf][1] = Al[w1];
            al[mf][2] = Al[w0 + 4]; al[mf][3] = Al[w1 + 4];
        }
#pragma unroll
        for (int nf = 0; nf < 4; nf++) {
            int nw = (wc * 32 + nf * 8 + g) * ROW_W + tg;
            uint32_t bh0 = Bh[nw], bh1 = Bh[nw + 4];
            uint32_t bl0 = Bl[nw], bl1 = Bl[nw + 4];
#pragma unroll
            for (int mf = 0; mf < 4; mf++) {
                mma16(acc[mf][nf], ah[mf], bh0, bh1);
                mma16(acc[mf][nf], ah[mf], bl0, bl1);
                mma16(acc[mf][nf], al[mf], bh0, bh1);
            }
        }
    }
    __syncthreads();

    // ---- epilogue: store h, compute per-head attention scores ----
    const int head = blockIdx.y * 4 + wc;
    float wl[4][2], wrt[4][2];
#pragma unroll
    for (int nf = 0; nf < 4; nf++) {
        int lc = nf * 8 + tg * 2;
        wl[nf][0]  = __ldg(a_l + ((size_t)t * HH + head) * HD + lc);
        wl[nf][1]  = __ldg(a_l + ((size_t)t * HH + head) * HD + lc + 1);
        wrt[nf][0] = __ldg(a_r + ((size_t)t * HH + head) * HD + lc);
        wrt[nf][1] = __ldg(a_r + ((size_t)t * HH + head) * HD + lc + 1);
    }
#pragma unroll
    for (int mf = 0; mf < 4; mf++) {
        int r0 = m0 + wr * 64 + mf * 16 + g;
        int r1 = r0 + 8;
        float dl0 = 0.f, dr0 = 0.f, dl1 = 0.f, dr1 = 0.f;
#pragma unroll
        for (int nf = 0; nf < 4; nf++) {
            int col = n0 + wc * 32 + nf * 8 + tg * 2;
            float c0 = acc[mf][nf][0], c1 = acc[mf][nf][1];
            float c2 = acc[mf][nf][2], c3 = acc[mf][nf][3];
            dl0 += c0 * wl[nf][0] + c1 * wl[nf][1];
            dr0 += c0 * wrt[nf][0] + c1 * wrt[nf][1];
            dl1 += c2 * wl[nf][0] + c3 * wl[nf][1];
            dr1 += c2 * wrt[nf][0] + c3 * wrt[nf][1];
            if (r0 < NN) *(float2*)&g_h[((size_t)t * NN + r0) * KD + col] = make_float2(c0, c1);
            if (r1 < NN) *(float2*)&g_h[((size_t)t * NN + r1) * KD + col] = make_float2(c2, c3);
        }
#pragma unroll
        for (int o = 1; o <= 2; o <<= 1) {
            dl0 += __shfl_xor_sync(0xffffffffu, dl0, o);
            dr0 += __shfl_xor_sync(0xffffffffu, dr0, o);
            dl1 += __shfl_xor_sync(0xffffffffu, dl1, o);
            dr1 += __shfl_xor_sync(0xffffffffu, dr1, o);
        }
        if (tg == 0) {
            if (r0 < NN) {
                g_sl[((size_t)t * NN + r0) * HH + head] = dl0;
                g_sr[((size_t)t * NN + r0) * HH + head] = dr0;
            }
            if (r1 < NN) {
                g_sl[((size_t)t * NN + r1) * HH + head] = dl1;
                g_sr[((size_t)t * NN + r1) * HH + head] = dr1;
            }
        }
    }
}

// ---------------- fused gather-aggregate + semantic attention ----------------
__global__ void __launch_bounds__(256) agg_sem_kernel(const float* __restrict__ att_w,
                                                      const float* __restrict__ att_b,
                                                      float* __restrict__ out) {
    int n = (blockIdx.x * blockDim.x + threadIdx.x) >> 5;
    int lane = threadIdx.x & 31;
    if (n >= NN) return;
    int head = lane >> 2;

    float4 o0[TT], o1[TT];

#pragma unroll
    for (int t = 0; t < TT; t++) {
        float srv = g_sr[((size_t)t * NN + n) * HH + head];
        int cnt = g_cnt[t * NN + n];
        cnt = cnt < CAP ? cnt : CAP;
        const int* adj = g_adj + ((size_t)t * NN + n) * CAP;
        float4 a0 = make_float4(0.f, 0.f, 0.f, 0.f);
        float4 a1 = make_float4(0.f, 0.f, 0.f, 0.f);
        float den = 0.f;
        int e = 0;
        for (; e + 4 <= cnt; e += 4) {
            int4 s4 = *(const int4*)(adj + e);
            float sc0 = __ldg(g_sl + ((size_t)t * NN + s4.x) * HH + head) + srv;
            float sc1 = __ldg(g_sl + ((size_t)t * NN + s4.y) * HH + head) + srv;
            float sc2 = __ldg(g_sl + ((size_t)t * NN + s4.z) * HH + head) + srv;
            float sc3 = __ldg(g_sl + ((size_t)t * NN + s4.w) * HH + head) + srv;
            const float4* p0 = (const float4*)(g_h + ((size_t)t * NN + s4.x) * KD + lane * 8);
            const float4* p1 = (const float4*)(g_h + ((size_t)t * NN + s4.y) * KD + lane * 8);
            const float4* p2 = (const float4*)(g_h + ((size_t)t * NN + s4.z) * KD + lane * 8);
            const float4* p3 = (const float4*)(g_h + ((size_t)t * NN + s4.w) * KD + lane * 8);
            float4 u00 = p0[0], u01 = p0[1];
            float4 u10 = p1[0], u11 = p1[1];
            float4 u20 = p2[0], u21 = p2[1];
            float4 u30 = p3[0], u31 = p3[1];
            sc0 = sc0 > 0.f ? sc0 : 0.2f * sc0;
            sc1 = sc1 > 0.f ? sc1 : 0.2f * sc1;
            sc2 = sc2 > 0.f ? sc2 : 0.2f * sc2;
            sc3 = sc3 > 0.f ? sc3 : 0.2f * sc3;
            float x0 = __expf(sc0), x1 = __expf(sc1), x2 = __expf(sc2), x3 = __expf(sc3);
            den += (x0 + x1) + (x2 + x3);
            a0.x += x0 * u00.x + x1 * u10.x + x2 * u20.x + x3 * u30.x;
            a0.y += x0 * u00.y + x1 * u10.y + x2 * u20.y + x3 * u30.y;
            a0.z += x0 * u00.z + x1 * u10.z + x2 * u20.z + x3 * u30.z;
            a0.w += x0 * u00.w + x1 * u10.w + x2 * u20.w + x3 * u30.w;
            a1.x += x0 * u01.x + x1 * u11.x + x2 * u21.x + x3 * u31.x;
            a1.y += x0 * u01.y + x1 * u11.y + x2 * u21.y + x3 * u31.y;
            a1.z += x0 * u01.z + x1 * u11.z + x2 * u21.z + x3 * u31.z;
            a1.w += x0 * u01.w + x1 * u11.w + x2 * u21.w + x3 * u31.w;
        }
        for (; e < cnt; e++) {
            int s0 = __ldg(adj + e);
            float sc0 = __ldg(g_sl + ((size_t)t * NN + s0) * HH + head) + srv;
            const float4* p0 = (const float4*)(g_h + ((size_t)t * NN + s0) * KD + lane * 8);
            float4 u0 = p0[0], u1 = p0[1];
            sc0 = sc0 > 0.f ? sc0 : 0.2f * sc0;
            float x0 = __expf(sc0);
            den += x0;
            a0.x += x0 * u0.x; a0.y += x0 * u0.y; a0.z += x0 * u0.z; a0.w += x0 * u0.w;
            a1.x += x0 * u1.x; a1.y += x0 * u1.y; a1.z += x0 * u1.z; a1.w += x0 * u1.w;
        }
        float inv = den > 0.f ? __frcp_rn(den) : 1.f;
        o0[t] = make_float4(a0.x * inv, a0.y * inv, a0.z * inv, a0.w * inv);
        o1[t] = make_float4(a1.x * inv, a1.y * inv, a1.z * inv, a1.w * inv);
    }

    // semantic attention
    float4 w0 = ((const float4*)att_w)[lane * 2];
    float4 w1 = ((const float4*)att_w)[lane * 2 + 1];
    float b = att_b[0];
    float4 acc0 = make_float4(0.f, 0.f, 0.f, 0.f);
    float4 acc1 = make_float4(0.f, 0.f, 0.f, 0.f);
#pragma unroll
    for (int t = 0; t < TT; t++) {
        float p = o0[t].x * w0.x + o0[t].y * w0.y + o0[t].z * w0.z + o0[t].w * w0.w
                + o1[t].x * w1.x + o1[t].y * w1.y + o1[t].z * w1.z + o1[t].w * w1.w;
#pragma unroll
        for (int o = 16; o; o >>= 1) p += __shfl_xor_sync(0xffffffffu, p, o);
        float att = p + b;
        acc0.x += att * o0[t].x; acc0.y += att * o0[t].y;
        acc0.z += att * o0[t].z; acc0.w += att * o0[t].w;
        acc1.x += att * o1[t].x; acc1.y += att * o1[t].y;
        acc1.z += att * o1[t].z; acc1.w += att * o1[t].w;
    }
    float4* dp = (float4*)(out + (size_t)n * KD + lane * 8);
    dp[0] = acc0;
    dp[1] = acc1;
}

extern "C" void kernel_launch(void* const* d_in, const int* in_sizes, int n_in,
                              void* d_out, int out_size) {
    const float* x     = (const float*)d_in[0];
    const int*   ei    = (const int*)d_in[1];
    const float* W     = (const float*)d_in[2];
    const float* a_l   = (const float*)d_in[3];
    const float* a_r   = (const float*)d_in[4];
    const float* att_w = (const float*)d_in[5];
    const float* att_b = (const float*)d_in[6];
    float* out = (float*)d_out;

    static int smem_set = 0;
    if (!smem_set) {
        cudaFuncSetAttribute(gemm_scores_kernel,
                             cudaFuncAttributeMaxDynamicSharedMemorySize, SM_TOTAL);
        smem_set = 1;
    }

    zero_cnt_kernel<<<(TT * NN + 255) / 256, 256>>>();
    build_kernel<<<(TT * EE + 255) / 256, 256>>>(ei);
    split_x_kernel<<<(NN * KD + 255) / 256, 256>>>(x);
    split_W_kernel<<<(TT * KD * KD + 255) / 256, 256>>>(W);

    dim3 ggrid((NN + 127) / 128, 2, TT);
    gemm_scores_kernel<<<ggrid, 256, SM_TOTAL>>>(a_l, a_r);

    agg_sem_kernel<<<(NN * 32 + 255) / 256, 256>>>(att_w, att_b, out);
}

// round 10
// speedup vs baseline: 1.1646x; 1.1646x over previous
#include <cuda_runtime.h>
#include <cuda_fp16.h>
#include <cstdint>

#define NN 50000
#define EE 400000
#define TT 3
#define KD 256
#define HH 8
#define HD 32
#define CAP 64   // max in-degree bucket (Poisson(8): max~26, huge margin)

// ---- scratch (device globals; no allocs allowed) ----
__device__ float g_h[TT * NN * KD];      // per-type transformed features
__device__ float g_sl[TT * NN * HH];
__device__ float g_sr[TT * NN * HH];
__device__ int   g_cnt[TT * NN];
__device__ int   g_adj[TT * NN * CAP];
__device__ __half g_xh[NN * KD];         // x hi plane (residual dropped; fp16 rel 2^-11)
__device__ __half g_Wh[TT * KD * KD];    // W^T hi plane  [t][n][k]
__device__ __half g_Wl[TT * KD * KD];    // W^T lo plane

static __device__ __forceinline__ uint32_t s2u(const void* p) {
    uint32_t a;
    asm("{ .reg .u64 t; cvta.to.shared.u64 t, %1; cvt.u32.u64 %0, t; }" : "=r"(a) : "l"(p));
    return a;
}
static __device__ __forceinline__ void cp16(uint32_t dst, const void* src, int sz) {
    asm volatile("cp.async.cg.shared.global [%0], [%1], 16, %2;"
                 :: "r"(dst), "l"(src), "r"(sz) : "memory");
}
static __device__ __forceinline__ void mma16(float* c, const uint32_t* a,
                                             uint32_t b0, uint32_t b1) {
    asm volatile(
        "mma.sync.aligned.m16n8k16.row.col.f32.f16.f16.f32 "
        "{%0,%1,%2,%3},{%4,%5,%6,%7},{%8,%9},{%0,%1,%2,%3};"
        : "+f"(c[0]), "+f"(c[1]), "+f"(c[2]), "+f"(c[3])
        : "r"(a[0]), "r"(a[1]), "r"(a[2]), "r"(a[3]), "r"(b0), "r"(b1));
}

// ---------------- prep: zero counters ----------------
__global__ void zero_cnt_kernel() {
    int i = blockIdx.x * blockDim.x + threadIdx.x;
    if (i < TT * NN) g_cnt[i] = 0;
}

// ---------------- prep: bucketed CSR build ----------------
__global__ void build_kernel(const int* __restrict__ ei) {
    int i = blockIdx.x * blockDim.x + threadIdx.x;
    if (i >= TT * EE) return;
    int t = i / EE, e = i - t * EE;
    int s = ei[t * 2 * EE + e];
    int d = ei[t * 2 * EE + EE + e];
    int pos = atomicAdd(&g_cnt[t * NN + d], 1);
    if (pos < CAP) g_adj[(t * NN + d) * CAP + pos] = s;
}

// ---------------- prep: fp16 planes ----------------
__global__ void split_x_kernel(const float* __restrict__ x) {
    int i = blockIdx.x * blockDim.x + threadIdx.x;
    if (i >= NN * KD) return;
    g_xh[i] = __float2half_rn(x[i]);
}
// W[t][k][n] -> planes [t][n][k]  (reads coalesced: n fastest)
__global__ void split_W_kernel(const float* __restrict__ W) {
    int i = blockIdx.x * blockDim.x + threadIdx.x;
    if (i >= TT * KD * KD) return;
    int n = i & 255, k = (i >> 8) & 255, t = i >> 16;
    float v = W[i];
    __half h = __float2half_rn(v);
    int o = (t << 16) + (n << 8) + k;
    g_Wh[o] = h;
    g_Wl[o] = __float2half_rn(v - __half2float(h));
}

// ---------------- 2-product fp16 mma.sync GEMM + fused score epilogue ----------------
// CTA 128x128xK256, BK=16, 8 warps 2x4, warp tile 64x32, 2 CTAs/SM.
// SMEM: 3 fp16 planes (Ah,Bh,Bl), 128 rows x 16 halves, row stride 12 words
// (bank (12g+tg)%32 all-distinct => conflict-free fragment loads). Double-buffered.
#define ROW_W 12                      // words per row
#define PLANE_W (128 * ROW_W)         // 1536 words per plane
#define BUF_W (3 * PLANE_W)           // 4608 words per buffer
#define SM_TOTAL (2 * BUF_W * 4)      // 36864 B

__global__ void __launch_bounds__(256, 2) gemm_scores_kernel(const float* __restrict__ a_l,
                                                             const float* __restrict__ a_r) {
    extern __shared__ char smraw[];
    uint32_t* smw = (uint32_t*)smraw;
    const uint32_t sbase = s2u(smraw);

    const int tid = threadIdx.x;
    const int wid = tid >> 5, lane = tid & 31;
    const int g = lane >> 2, tg = lane & 3;
    const int wr = wid >> 2, wc = wid & 3;
    const int t = blockIdx.z;
    const int m0 = blockIdx.x * 128, n0 = blockIdx.y * 128;

    float acc[4][4][4];
#pragma unroll
    for (int i = 0; i < 4; i++)
#pragma unroll
        for (int j = 0; j < 4; j++)
#pragma unroll
            for (int q = 0; q < 4; q++) acc[i][j][q] = 0.f;

    const int lr = tid >> 1, half = tid & 1;     // load row / 16B-half
    const int gr = m0 + lr;                       // A global row
    const int nr = n0 + lr;                       // B global row (n index)

    auto loadTile = [&](int kt, int buf) {
        const int k0 = kt * 16;
        uint32_t sb = sbase + (uint32_t)buf * BUF_W * 4;
        uint32_t wo = (uint32_t)(lr * ROW_W + half * 4) * 4;
        int asz = gr < NN ? 16 : 0;
        cp16(sb + wo, g_xh + (size_t)gr * KD + k0 + half * 8, asz);
        size_t woff = ((size_t)t * KD + nr) * KD + k0 + half * 8;
        cp16(sb + PLANE_W * 4 + wo, g_Wh + woff, 16);
        cp16(sb + 2 * PLANE_W * 4 + wo, g_Wl + woff, 16);
        asm volatile("cp.async.commit_group;" ::: "memory");
    };

    loadTile(0, 0);

    for (int kt = 0; kt < 16; kt++) {
        const int buf = kt & 1;
        if (kt < 15) loadTile(kt + 1, buf ^ 1);
        if (kt < 15) asm volatile("cp.async.wait_group 1;" ::: "memory");
        else         asm volatile("cp.async.wait_group 0;" ::: "memory");
        __syncthreads();

        const uint32_t* Ah = smw + buf * BUF_W;
        const uint32_t* Bh = Ah + PLANE_W;
        const uint32_t* Bl = Ah + 2 * PLANE_W;

        uint32_t ah[4][4];
#pragma unroll
        for (int mf = 0; mf < 4; mf++) {
            int w0 = (wr * 64 + mf * 16 + g) * ROW_W + tg;
            int w1 = w0 + 8 * ROW_W;
            ah[mf][0] = Ah[w0]; ah[mf][1] = Ah[w1];
            ah[mf][2] = Ah[w0 + 4]; ah[mf][3] = Ah[w1 + 4];
        }
#pragma unroll
        for (int nf = 0; nf < 4; nf++) {
            int nw = (wc * 32 + nf * 8 + g) * ROW_W + tg;
            uint32_t bh0 = Bh[nw], bh1 = Bh[nw + 4];
            uint32_t bl0 = Bl[nw], bl1 = Bl[nw + 4];
#pragma unroll
            for (int mf = 0; mf < 4; mf++) {
                mma16(acc[mf][nf], ah[mf], bh0, bh1);
                mma16(acc[mf][nf], ah[mf], bl0, bl1);
            }
        }
        __syncthreads();
    }

    // ---- epilogue: store h, compute per-head attention scores ----
    const int head = blockIdx.y * 4 + wc;
    float wl[4][2], wrt[4][2];
#pragma unroll
    for (int nf = 0; nf < 4; nf++) {
        int lc = nf * 8 + tg * 2;
        wl[nf][0]  = __ldg(a_l + ((size_t)t * HH + head) * HD + lc);
        wl[nf][1]  = __ldg(a_l + ((size_t)t * HH + head) * HD + lc + 1);
        wrt[nf][0] = __ldg(a_r + ((size_t)t * HH + head) * HD + lc);
        wrt[nf][1] = __ldg(a_r + ((size_t)t * HH + head) * HD + lc + 1);
    }
#pragma unroll
    for (int mf = 0; mf < 4; mf++) {
        int r0 = m0 + wr * 64 + mf * 16 + g;
        int r1 = r0 + 8;
        float dl0 = 0.f, dr0 = 0.f, dl1 = 0.f, dr1 = 0.f;
#pragma unroll
        for (int nf = 0; nf < 4; nf++) {
            int col = n0 + wc * 32 + nf * 8 + tg * 2;
            float c0 = acc[mf][nf][0], c1 = acc[mf][nf][1];
            float c2 = acc[mf][nf][2], c3 = acc[mf][nf][3];
            dl0 += c0 * wl[nf][0] + c1 * wl[nf][1];
            dr0 += c0 * wrt[nf][0] + c1 * wrt[nf][1];
            dl1 += c2 * wl[nf][0] + c3 * wl[nf][1];
            dr1 += c2 * wrt[nf][0] + c3 * wrt[nf][1];
            if (r0 < NN) *(float2*)&g_h[((size_t)t * NN + r0) * KD + col] = make_float2(c0, c1);
            if (r1 < NN) *(float2*)&g_h[((size_t)t * NN + r1) * KD + col] = make_float2(c2, c3);
        }
#pragma unroll
        for (int o = 1; o <= 2; o <<= 1) {
            dl0 += __shfl_xor_sync(0xffffffffu, dl0, o);
            dr0 += __shfl_xor_sync(0xffffffffu, dr0, o);
            dl1 += __shfl_xor_sync(0xffffffffu, dl1, o);
            dr1 += __shfl_xor_sync(0xffffffffu, dr1, o);
        }
        if (tg == 0) {
            if (r0 < NN) {
                g_sl[((size_t)t * NN + r0) * HH + head] = dl0;
                g_sr[((size_t)t * NN + r0) * HH + head] = dr0;
            }
            if (r1 < NN) {
                g_sl[((size_t)t * NN + r1) * HH + head] = dl1;
                g_sr[((size_t)t * NN + r1) * HH + head] = dr1;
            }
        }
    }
}

// ---------------- fused gather-aggregate + semantic attention ----------------
__global__ void __launch_bounds__(256) agg_sem_kernel(const float* __restrict__ att_w,
                                                      const float* __restrict__ att_b,
                                                      float* __restrict__ out) {
    int n = (blockIdx.x * blockDim.x + threadIdx.x) >> 5;
    int lane = threadIdx.x & 31;
    if (n >= NN) return;
    int head = lane >> 2;

    float4 o0[TT], o1[TT];

#pragma unroll
    for (int t = 0; t < TT; t++) {
        float srv = g_sr[((size_t)t * NN + n) * HH + head];
        int cnt = g_cnt[t * NN + n];
        cnt = cnt < CAP ? cnt : CAP;
        const int* adj = g_adj + ((size_t)t * NN + n) * CAP;
        float4 a0 = make_float4(0.f, 0.f, 0.f, 0.f);
        float4 a1 = make_float4(0.f, 0.f, 0.f, 0.f);
        float den = 0.f;
        int e = 0;
        for (; e + 4 <= cnt; e += 4) {
            int4 s4 = *(const int4*)(adj + e);
            float sc0 = __ldg(g_sl + ((size_t)t * NN + s4.x) * HH + head) + srv;
            float sc1 = __ldg(g_sl + ((size_t)t * NN + s4.y) * HH + head) + srv;
            float sc2 = __ldg(g_sl + ((size_t)t * NN + s4.z) * HH + head) + srv;
            float sc3 = __ldg(g_sl + ((size_t)t * NN + s4.w) * HH + head) + srv;
            const float4* p0 = (const float4*)(g_h + ((size_t)t * NN + s4.x) * KD + lane * 8);
            const float4* p1 = (const float4*)(g_h + ((size_t)t * NN + s4.y) * KD + lane * 8);
            const float4* p2 = (const float4*)(g_h + ((size_t)t * NN + s4.z) * KD + lane * 8);
            const float4* p3 = (const float4*)(g_h + ((size_t)t * NN + s4.w) * KD + lane * 8);
            float4 u00 = p0[0], u01 = p0[1];
            float4 u10 = p1[0], u11 = p1[1];
            float4 u20 = p2[0], u21 = p2[1];
            float4 u30 = p3[0], u31 = p3[1];
            sc0 = sc0 > 0.f ? sc0 : 0.2f * sc0;
            sc1 = sc1 > 0.f ? sc1 : 0.2f * sc1;
            sc2 = sc2 > 0.f ? sc2 : 0.2f * sc2;
            sc3 = sc3 > 0.f ? sc3 : 0.2f * sc3;
            float x0 = __expf(sc0), x1 = __expf(sc1), x2 = __expf(sc2), x3 = __expf(sc3);
            den += (x0 + x1) + (x2 + x3);
            a0.x += x0 * u00.x + x1 * u10.x + x2 * u20.x + x3 * u30.x;
            a0.y += x0 * u00.y + x1 * u10.y + x2 * u20.y + x3 * u30.y;
            a0.z += x0 * u00.z + x1 * u10.z + x2 * u20.z + x3 * u30.z;
            a0.w += x0 * u00.w + x1 * u10.w + x2 * u20.w + x3 * u30.w;
            a1.x += x0 * u01.x + x1 * u11.x + x2 * u21.x + x3 * u31.x;
            a1.y += x0 * u01.y + x1 * u11.y + x2 * u21.y + x3 * u31.y;
            a1.z += x0 * u01.z + x1 * u11.z + x2 * u21.z + x3 * u31.z;
            a1.w += x0 * u01.w + x1 * u11.w + x2 * u21.w + x3 * u31.w;
        }
        for (; e < cnt; e++) {
            int s0 = __ldg(adj + e);
            float sc0 = __ldg(g_sl + ((size_t)t * NN + s0) * HH + head) + srv;
            const float4* p0 = (const float4*)(g_h + ((size_t)t * NN + s0) * KD + lane * 8);
            float4 u0 = p0[0], u1 = p0[1];
            sc0 = sc0 > 0.f ? sc0 : 0.2f * sc0;
            float x0 = __expf(sc0);
            den += x0;
            a0.x += x0 * u0.x; a0.y += x0 * u0.y; a0.z += x0 * u0.z; a0.w += x0 * u0.w;
            a1.x += x0 * u1.x; a1.y += x0 * u1.y; a1.z += x0 * u1.z; a1.w += x0 * u1.w;
        }
        float inv = den > 0.f ? __frcp_rn(den) : 1.f;
        o0[t] = make_float4(a0.x * inv, a0.y * inv, a0.z * inv, a0.w * inv);
        o1[t] = make_float4(a1.x * inv, a1.y * inv, a1.z * inv, a1.w * inv);
    }

    // semantic attention
    float4 w0 = ((const float4*)att_w)[lane * 2];
    float4 w1 = ((const float4*)att_w)[lane * 2 + 1];
    float b = att_b[0];
    float4 acc0 = make_float4(0.f, 0.f, 0.f, 0.f);
    float4 acc1 = make_float4(0.f, 0.f, 0.f, 0.f);
#pragma unroll
    for (int t = 0; t < TT; t++) {
        float p = o0[t].x * w0.x + o0[t].y * w0.y + o0[t].z * w0.z + o0[t].w * w0.w
                + o1[t].x * w1.x + o1[t].y * w1.y + o1[t].z * w1.z + o1[t].w * w1.w;
#pragma unroll
        for (int o = 16; o; o >>= 1) p += __shfl_xor_sync(0xffffffffu, p, o);
        float att = p + b;
        acc0.x += att * o0[t].x; acc0.y += att * o0[t].y;
        acc0.z += att * o0[t].z; acc0.w += att * o0[t].w;
        acc1.x += att * o1[t].x; acc1.y += att * o1[t].y;
        acc1.z += att * o1[t].z; acc1.w += att * o1[t].w;
    }
    float4* dp = (float4*)(out + (size_t)n * KD + lane * 8);
    dp[0] = acc0;
    dp[1] = acc1;
}

extern "C" void kernel_launch(void* const* d_in, const int* in_sizes, int n_in,
                              void* d_out, int out_size) {
    const float* x     = (const float*)d_in[0];
    const int*   ei    = (const int*)d_in[1];
    const float* W     = (const float*)d_in[2];
    const float* a_l   = (const float*)d_in[3];
    const float* a_r   = (const float*)d_in[4];
    const float* att_w = (const float*)d_in[5];
    const float* att_b = (const float*)d_in[6];
    float* out = (float*)d_out;

    static int smem_set = 0;
    if (!smem_set) {
        cudaFuncSetAttribute(gemm_scores_kernel,
                             cudaFuncAttributeMaxDynamicSharedMemorySize, SM_TOTAL);
        smem_set = 1;
    }

    zero_cnt_kernel<<<(TT * NN + 255) / 256, 256>>>();
    build_kernel<<<(TT * EE + 255) / 256, 256>>>(ei);
    split_x_kernel<<<(NN * KD + 255) / 256, 256>>>(x);
    split_W_kernel<<<(TT * KD * KD + 255) / 256, 256>>>(W);

    dim3 ggrid((NN + 127) / 128, 2, TT);
    gemm_scores_kernel<<<ggrid, 256, SM_TOTAL>>>(a_l, a_r);

    agg_sem_kernel<<<(NN * 32 + 255) / 256, 256>>>(att_w, att_b, out);
}

// round 11
// speedup vs baseline: 1.3547x; 1.1633x over previous
#include <cuda_runtime.h>
#include <cuda_fp16.h>
#include <cstdint>

#define NN 50000
#define EE 400000
#define TT 3
#define KD 256
#define HH 8
#define HD 32
#define CAP 64   // max in-degree bucket (Poisson(8): max~26, huge margin)

// ---- scratch (device globals; no allocs allowed) ----
__device__ __half g_h[TT * NN * KD];     // per-type transformed features (fp16 storage)
__device__ float g_sl[TT * NN * HH];
__device__ float g_sr[TT * NN * HH];
__device__ int   g_cnt[TT * NN];
__device__ int   g_adj[TT * NN * CAP];
__device__ __half g_xh[NN * KD];         // x hi plane (fp16 rn)
__device__ __half g_Wh[TT * KD * KD];    // W^T hi plane  [t][n][k]
__device__ __half g_Wl[TT * KD * KD];    // W^T lo plane

static __device__ __forceinline__ uint32_t s2u(const void* p) {
    uint32_t a;
    asm("{ .reg .u64 t; cvta.to.shared.u64 t, %1; cvt.u32.u64 %0, t; }" : "=r"(a) : "l"(p));
    return a;
}
static __device__ __forceinline__ void cp16(uint32_t dst, const void* src, int sz) {
    asm volatile("cp.async.cg.shared.global [%0], [%1], 16, %2;"
                 :: "r"(dst), "l"(src), "r"(sz) : "memory");
}
static __device__ __forceinline__ void mma16(float* c, const uint32_t* a,
                                             uint32_t b0, uint32_t b1) {
    asm volatile(
        "mma.sync.aligned.m16n8k16.row.col.f32.f16.f16.f32 "
        "{%0,%1,%2,%3},{%4,%5,%6,%7},{%8,%9},{%0,%1,%2,%3};"
        : "+f"(c[0]), "+f"(c[1]), "+f"(c[2]), "+f"(c[3])
        : "r"(a[0]), "r"(a[1]), "r"(a[2]), "r"(a[3]), "r"(b0), "r"(b1));
}

// ---------------- prep: zero counters ----------------
__global__ void zero_cnt_kernel() {
    int i = blockIdx.x * blockDim.x + threadIdx.x;
    if (i < TT * NN) g_cnt[i] = 0;
}

// ---------------- prep: bucketed CSR build ----------------
__global__ void build_kernel(const int* __restrict__ ei) {
    int i = blockIdx.x * blockDim.x + threadIdx.x;
    if (i >= TT * EE) return;
    int t = i / EE, e = i - t * EE;
    int s = ei[t * 2 * EE + e];
    int d = ei[t * 2 * EE + EE + e];
    int pos = atomicAdd(&g_cnt[t * NN + d], 1);
    if (pos < CAP) g_adj[(t * NN + d) * CAP + pos] = s;
}

// ---------------- prep: fp16 planes ----------------
__global__ void split_x_kernel(const float* __restrict__ x) {
    int i = blockIdx.x * blockDim.x + threadIdx.x;
    if (i >= NN * KD) return;
    g_xh[i] = __float2half_rn(x[i]);
}
// W[t][k][n] -> planes [t][n][k]  (reads coalesced: n fastest)
__global__ void split_W_kernel(const float* __restrict__ W) {
    int i = blockIdx.x * blockDim.x + threadIdx.x;
    if (i >= TT * KD * KD) return;
    int n = i & 255, k = (i >> 8) & 255, t = i >> 16;
    float v = W[i];
    __half h = __float2half_rn(v);
    int o = (t << 16) + (n << 8) + k;
    g_Wh[o] = h;
    g_Wl[o] = __float2half_rn(v - __half2float(h));
}

// ---------------- 2-product fp16 mma.sync GEMM + fused score epilogue ----------------
// CTA 128x128xK256, BK=16, 8 warps 2x4, warp tile 64x32, 2 CTAs/SM.
// SMEM: 3 fp16 planes (Ah,Bh,Bl), 128 rows x 16 halves, row stride 12 words
// (bank (12g+tg)%32 all-distinct => conflict-free fragment loads). Double-buffered.
#define ROW_W 12                      // words per row
#define PLANE_W (128 * ROW_W)         // 1536 words per plane
#define BUF_W (3 * PLANE_W)           // 4608 words per buffer
#define SM_TOTAL (2 * BUF_W * 4)      // 36864 B

__global__ void __launch_bounds__(256, 2) gemm_scores_kernel(const float* __restrict__ a_l,
                                                             const float* __restrict__ a_r) {
    extern __shared__ char smraw[];
    uint32_t* smw = (uint32_t*)smraw;
    const uint32_t sbase = s2u(smraw);

    const int tid = threadIdx.x;
    const int wid = tid >> 5, lane = tid & 31;
    const int g = lane >> 2, tg = lane & 3;
    const int wr = wid >> 2, wc = wid & 3;
    const int t = blockIdx.z;
    const int m0 = blockIdx.x * 128, n0 = blockIdx.y * 128;

    float acc[4][4][4];
#pragma unroll
    for (int i = 0; i < 4; i++)
#pragma unroll
        for (int j = 0; j < 4; j++)
#pragma unroll
            for (int q = 0; q < 4; q++) acc[i][j][q] = 0.f;

    const int lr = tid >> 1, half = tid & 1;     // load row / 16B-half
    const int gr = m0 + lr;                       // A global row
    const int nr = n0 + lr;                       // B global row (n index)

    auto loadTile = [&](int kt, int buf) {
        const int k0 = kt * 16;
        uint32_t sb = sbase + (uint32_t)buf * BUF_W * 4;
        uint32_t wo = (uint32_t)(lr * ROW_W + half * 4) * 4;
        int asz = gr < NN ? 16 : 0;
        cp16(sb + wo, g_xh + (size_t)gr * KD + k0 + half * 8, asz);
        size_t woff = ((size_t)t * KD + nr) * KD + k0 + half * 8;
        cp16(sb + PLANE_W * 4 + wo, g_Wh + woff, 16);
        cp16(sb + 2 * PLANE_W * 4 + wo, g_Wl + woff, 16);
        asm volatile("cp.async.commit_group;" ::: "memory");
    };

    loadTile(0, 0);

    for (int kt = 0; kt < 16; kt++) {
        const int buf = kt & 1;
        if (kt < 15) loadTile(kt + 1, buf ^ 1);
        if (kt < 15) asm volatile("cp.async.wait_group 1;" ::: "memory");
        else         asm volatile("cp.async.wait_group 0;" ::: "memory");
        __syncthreads();

        const uint32_t* Ah = smw + buf * BUF_W;
        const uint32_t* Bh = Ah + PLANE_W;
        const uint32_t* Bl = Ah + 2 * PLANE_W;

        uint32_t ah[4][4];
#pragma unroll
        for (int mf = 0; mf < 4; mf++) {
            int w0 = (wr * 64 + mf * 16 + g) * ROW_W + tg;
            int w1 = w0 + 8 * ROW_W;
            ah[mf][0] = Ah[w0]; ah[mf][1] = Ah[w1];
            ah[mf][2] = Ah[w0 + 4]; ah[mf][3] = Ah[w1 + 4];
        }
#pragma unroll
        for (int nf = 0; nf < 4; nf++) {
            int nw = (wc * 32 + nf * 8 + g) * ROW_W + tg;
            uint32_t bh0 = Bh[nw], bh1 = Bh[nw + 4];
            uint32_t bl0 = Bl[nw], bl1 = Bl[nw + 4];
#pragma unroll
            for (int mf = 0; mf < 4; mf++) {
                mma16(acc[mf][nf], ah[mf], bh0, bh1);
                mma16(acc[mf][nf], ah[mf], bl0, bl1);
            }
        }
        __syncthreads();
    }

    // ---- epilogue: store h (fp16), compute per-head attention scores (fp32) ----
    const int head = blockIdx.y * 4 + wc;
    float wl[4][2], wrt[4][2];
#pragma unroll
    for (int nf = 0; nf < 4; nf++) {
        int lc = nf * 8 + tg * 2;
        wl[nf][0]  = __ldg(a_l + ((size_t)t * HH + head) * HD + lc);
        wl[nf][1]  = __ldg(a_l + ((size_t)t * HH + head) * HD + lc + 1);
        wrt[nf][0] = __ldg(a_r + ((size_t)t * HH + head) * HD + lc);
        wrt[nf][1] = __ldg(a_r + ((size_t)t * HH + head) * HD + lc + 1);
    }
#pragma unroll
    for (int mf = 0; mf < 4; mf++) {
        int r0 = m0 + wr * 64 + mf * 16 + g;
        int r1 = r0 + 8;
        float dl0 = 0.f, dr0 = 0.f, dl1 = 0.f, dr1 = 0.f;
#pragma unroll
        for (int nf = 0; nf < 4; nf++) {
            int col = n0 + wc * 32 + nf * 8 + tg * 2;
            float c0 = acc[mf][nf][0], c1 = acc[mf][nf][1];
            float c2 = acc[mf][nf][2], c3 = acc[mf][nf][3];
            dl0 += c0 * wl[nf][0] + c1 * wl[nf][1];
            dr0 += c0 * wrt[nf][0] + c1 * wrt[nf][1];
            dl1 += c2 * wl[nf][0] + c3 * wl[nf][1];
            dr1 += c2 * wrt[nf][0] + c3 * wrt[nf][1];
            if (r0 < NN)
                *(__half2*)&g_h[((size_t)t * NN + r0) * KD + col] =
                    __floats2half2_rn(c0, c1);
            if (r1 < NN)
                *(__half2*)&g_h[((size_t)t * NN + r1) * KD + col] =
                    __floats2half2_rn(c2, c3);
        }
#pragma unroll
        for (int o = 1; o <= 2; o <<= 1) {
            dl0 += __shfl_xor_sync(0xffffffffu, dl0, o);
            dr0 += __shfl_xor_sync(0xffffffffu, dr0, o);
            dl1 += __shfl_xor_sync(0xffffffffu, dl1, o);
            dr1 += __shfl_xor_sync(0xffffffffu, dr1, o);
        }
        if (tg == 0) {
            if (r0 < NN) {
                g_sl[((size_t)t * NN + r0) * HH + head] = dl0;
                g_sr[((size_t)t * NN + r0) * HH + head] = dr0;
            }
            if (r1 < NN) {
                g_sl[((size_t)t * NN + r1) * HH + head] = dl1;
                g_sr[((size_t)t * NN + r1) * HH + head] = dr1;
            }
        }
    }
}

// ---------------- fused gather-aggregate + semantic attention ----------------
// One warp per dst node; fp16 h gather (16B/lane/edge); all state in registers.
__global__ void __launch_bounds__(256) agg_sem_kernel(const float* __restrict__ att_w,
                                                      const float* __restrict__ att_b,
                                                      float* __restrict__ out) {
    int n = (blockIdx.x * blockDim.x + threadIdx.x) >> 5;
    int lane = threadIdx.x & 31;
    if (n >= NN) return;
    int head = lane >> 2;

    float4 o0[TT], o1[TT];

#pragma unroll
    for (int t = 0; t < TT; t++) {
        float srv = g_sr[((size_t)t * NN + n) * HH + head];
        int cnt = g_cnt[t * NN + n];
        cnt = cnt < CAP ? cnt : CAP;
        const int* adj = g_adj + ((size_t)t * NN + n) * CAP;
        float4 a0 = make_float4(0.f, 0.f, 0.f, 0.f);
        float4 a1 = make_float4(0.f, 0.f, 0.f, 0.f);
        float den = 0.f;
        int e = 0;
        for (; e + 4 <= cnt; e += 4) {
            int4 s4 = *(const int4*)(adj + e);
            float sc0 = __ldg(g_sl + ((size_t)t * NN + s4.x) * HH + head) + srv;
            float sc1 = __ldg(g_sl + ((size_t)t * NN + s4.y) * HH + head) + srv;
            float sc2 = __ldg(g_sl + ((size_t)t * NN + s4.z) * HH + head) + srv;
            float sc3 = __ldg(g_sl + ((size_t)t * NN + s4.w) * HH + head) + srv;
            uint4 r0v = *(const uint4*)(g_h + ((size_t)t * NN + s4.x) * KD + lane * 8);
            uint4 r1v = *(const uint4*)(g_h + ((size_t)t * NN + s4.y) * KD + lane * 8);
            uint4 r2v = *(const uint4*)(g_h + ((size_t)t * NN + s4.z) * KD + lane * 8);
            uint4 r3v = *(const uint4*)(g_h + ((size_t)t * NN + s4.w) * KD + lane * 8);
            sc0 = sc0 > 0.f ? sc0 : 0.2f * sc0;
            sc1 = sc1 > 0.f ? sc1 : 0.2f * sc1;
            sc2 = sc2 > 0.f ? sc2 : 0.2f * sc2;
            sc3 = sc3 > 0.f ? sc3 : 0.2f * sc3;
            float x0 = __expf(sc0), x1 = __expf(sc1), x2 = __expf(sc2), x3 = __expf(sc3);
            den += (x0 + x1) + (x2 + x3);
            const __half2* h0 = (const __half2*)&r0v;
            const __half2* h1 = (const __half2*)&r1v;
            const __half2* h2 = (const __half2*)&r2v;
            const __half2* h3 = (const __half2*)&r3v;
            float2 f;
            f = __half22float2(h0[0]); a0.x += x0 * f.x; a0.y += x0 * f.y;
            f = __half22float2(h0[1]); a0.z += x0 * f.x; a0.w += x0 * f.y;
            f = __half22float2(h0[2]); a1.x += x0 * f.x; a1.y += x0 * f.y;
            f = __half22float2(h0[3]); a1.z += x0 * f.x; a1.w += x0 * f.y;
            f = __half22float2(h1[0]); a0.x += x1 * f.x; a0.y += x1 * f.y;
            f = __half22float2(h1[1]); a0.z += x1 * f.x; a0.w += x1 * f.y;
            f = __half22float2(h1[2]); a1.x += x1 * f.x; a1.y += x1 * f.y;
            f = __half22float2(h1[3]); a1.z += x1 * f.x; a1.w += x1 * f.y;
            f = __half22float2(h2[0]); a0.x += x2 * f.x; a0.y += x2 * f.y;
            f = __half22float2(h2[1]); a0.z += x2 * f.x; a0.w += x2 * f.y;
            f = __half22float2(h2[2]); a1.x += x2 * f.x; a1.y += x2 * f.y;
            f = __half22float2(h2[3]); a1.z += x2 * f.x; a1.w += x2 * f.y;
            f = __half22float2(h3[0]); a0.x += x3 * f.x; a0.y += x3 * f.y;
            f = __half22float2(h3[1]); a0.z += x3 * f.x; a0.w += x3 * f.y;
            f = __half22float2(h3[2]); a1.x += x3 * f.x; a1.y += x3 * f.y;
            f = __half22float2(h3[3]); a1.z += x3 * f.x; a1.w += x3 * f.y;
        }
        for (; e < cnt; e++) {
            int s0 = __ldg(adj + e);
            float sc0 = __ldg(g_sl + ((size_t)t * NN + s0) * HH + head) + srv;
            uint4 rv = *(const uint4*)(g_h + ((size_t)t * NN + s0) * KD + lane * 8);
            sc0 = sc0 > 0.f ? sc0 : 0.2f * sc0;
            float x0 = __expf(sc0);
            den += x0;
            const __half2* hp = (const __half2*)&rv;
            float2 f;
            f = __half22float2(hp[0]); a0.x += x0 * f.x; a0.y += x0 * f.y;
            f = __half22float2(hp[1]); a0.z += x0 * f.x; a0.w += x0 * f.y;
            f = __half22float2(hp[2]); a1.x += x0 * f.x; a1.y += x0 * f.y;
            f = __half22float2(hp[3]); a1.z += x0 * f.x; a1.w += x0 * f.y;
        }
        float inv = den > 0.f ? __frcp_rn(den) : 1.f;
        o0[t] = make_float4(a0.x * inv, a0.y * inv, a0.z * inv, a0.w * inv);
        o1[t] = make_float4(a1.x * inv, a1.y * inv, a1.z * inv, a1.w * inv);
    }

    // semantic attention
    float4 w0 = ((const float4*)att_w)[lane * 2];
    float4 w1 = ((const float4*)att_w)[lane * 2 + 1];
    float b = att_b[0];
    float4 acc0 = make_float4(0.f, 0.f, 0.f, 0.f);
    float4 acc1 = make_float4(0.f, 0.f, 0.f, 0.f);
#pragma unroll
    for (int t = 0; t < TT; t++) {
        float p = o0[t].x * w0.x + o0[t].y * w0.y + o0[t].z * w0.z + o0[t].w * w0.w
                + o1[t].x * w1.x + o1[t].y * w1.y + o1[t].z * w1.z + o1[t].w * w1.w;
#pragma unroll
        for (int o = 16; o; o >>= 1) p += __shfl_xor_sync(0xffffffffu, p, o);
        float att = p + b;
        acc0.x += att * o0[t].x; acc0.y += att * o0[t].y;
        acc0.z += att * o0[t].z; acc0.w += att * o0[t].w;
        acc1.x += att * o1[t].x; acc1.y += att * o1[t].y;
        acc1.z += att * o1[t].z; acc1.w += att * o1[t].w;
    }
    float4* dp = (float4*)(out + (size_t)n * KD + lane * 8);
    dp[0] = acc0;
    dp[1] = acc1;
}

extern "C" void kernel_launch(void* const* d_in, const int* in_sizes, int n_in,
                              void* d_out, int out_size) {
    const float* x     = (const float*)d_in[0];
    const int*   ei    = (const int*)d_in[1];
    const float* W     = (const float*)d_in[2];
    const float* a_l   = (const float*)d_in[3];
    const float* a_r   = (const float*)d_in[4];
    const float* att_w = (const float*)d_in[5];
    const float* att_b = (const float*)d_in[6];
    float* out = (float*)d_out;

    static int smem_set = 0;
    if (!smem_set) {
        cudaFuncSetAttribute(gemm_scores_kernel,
                             cudaFuncAttributeMaxDynamicSharedMemorySize, SM_TOTAL);
        smem_set = 1;
    }

    zero_cnt_kernel<<<(TT * NN + 255) / 256, 256>>>();
    build_kernel<<<(TT * EE + 255) / 256, 256>>>(ei);
    split_x_kernel<<<(NN * KD + 255) / 256, 256>>>(x);
    split_W_kernel<<<(TT * KD * KD + 255) / 256, 256>>>(W);

    dim3 ggrid((NN + 127) / 128, 2, TT);
    gemm_scores_kernel<<<ggrid, 256, SM_TOTAL>>>(a_l, a_r);

    agg_sem_kernel<<<(NN * 32 + 255) / 256, 256>>>(att_w, att_b, out);
}

// round 12
// speedup vs baseline: 1.6052x; 1.1849x over previous
#include <cuda_runtime.h>
#include <cuda_fp16.h>
#include <cstdint>

#define NN 50000
#define EE 400000
#define TT 3
#define KD 256
#define HH 8
#define HD 32
#define CAP 64   // max in-degree bucket (Poisson(8): max~26, huge margin)

// ---- scratch (device globals; no allocs allowed) ----
__device__ __half g_h[TT * NN * KD];     // per-type transformed features (fp16 storage)
__device__ float g_sl[TT * NN * HH];
__device__ float g_sr[TT * NN * HH];
__device__ int   g_cnt[TT * NN];
__device__ int   g_adj[TT * NN * CAP];
__device__ __half g_xh[NN * KD];         // x (fp16 rn)
__device__ __half g_Wh[TT * KD * KD];    // W^T (fp16 rn)  [t][n][k]

static __device__ __forceinline__ uint32_t s2u(const void* p) {
    uint32_t a;
    asm("{ .reg .u64 t; cvta.to.shared.u64 t, %1; cvt.u32.u64 %0, t; }" : "=r"(a) : "l"(p));
    return a;
}
static __device__ __forceinline__ void cp16(uint32_t dst, const void* src, int sz) {
    asm volatile("cp.async.cg.shared.global [%0], [%1], 16, %2;"
                 :: "r"(dst), "l"(src), "r"(sz) : "memory");
}
static __device__ __forceinline__ void mma16(float* c, const uint32_t* a,
                                             uint32_t b0, uint32_t b1) {
    asm volatile(
        "mma.sync.aligned.m16n8k16.row.col.f32.f16.f16.f32 "
        "{%0,%1,%2,%3},{%4,%5,%6,%7},{%8,%9},{%0,%1,%2,%3};"
        : "+f"(c[0]), "+f"(c[1]), "+f"(c[2]), "+f"(c[3])
        : "r"(a[0]), "r"(a[1]), "r"(a[2]), "r"(a[3]), "r"(b0), "r"(b1));
}

// ---------------- prep: zero counters ----------------
__global__ void zero_cnt_kernel() {
    int i = blockIdx.x * blockDim.x + threadIdx.x;
    if (i < TT * NN) g_cnt[i] = 0;
}

// ---------------- prep: bucketed CSR build ----------------
__global__ void build_kernel(const int* __restrict__ ei) {
    int i = blockIdx.x * blockDim.x + threadIdx.x;
    if (i >= TT * EE) return;
    int t = i / EE, e = i - t * EE;
    int s = ei[t * 2 * EE + e];
    int d = ei[t * 2 * EE + EE + e];
    int pos = atomicAdd(&g_cnt[t * NN + d], 1);
    if (pos < CAP) g_adj[(t * NN + d) * CAP + pos] = s;
}

// ---------------- prep: fp16 conversion of x and W^T (fused) ----------------
__global__ void convert_kernel(const float* __restrict__ x, const float* __restrict__ W) {
    int i = blockIdx.x * blockDim.x + threadIdx.x;
    if (i < NN * KD) {
        g_xh[i] = __float2half_rn(x[i]);
    } else if (i < NN * KD + TT * KD * KD) {
        int j = i - NN * KD;
        int n = j & 255, k = (j >> 8) & 255, t = j >> 16;
        g_Wh[(t << 16) + (n << 8) + k] = __float2half_rn(W[j]);
    }
}

// ---------------- fp16 mma.sync GEMM + fused score epilogue ----------------
// CTA 128x128xK256, BK=16, 8 warps 2x4, warp tile 64x32, 2 CTAs/SM.
// SMEM: 2 fp16 planes (A,B), 128 rows x 16 halves, row stride 12 words
// (bank (12g+tg)%32 all-distinct => conflict-free fragment loads). Double-buffered.
#define ROW_W 12                      // words per row
#define PLANE_W (128 * ROW_W)         // 1536 words per plane
#define BUF_W (2 * PLANE_W)           // 3072 words per buffer
#define SM_TOTAL (2 * BUF_W * 4)      // 24576 B

__global__ void __launch_bounds__(256, 2) gemm_scores_kernel(const float* __restrict__ a_l,
                                                             const float* __restrict__ a_r) {
    extern __shared__ char smraw[];
    uint32_t* smw = (uint32_t*)smraw;
    const uint32_t sbase = s2u(smraw);

    const int tid = threadIdx.x;
    const int wid = tid >> 5, lane = tid & 31;
    const int g = lane >> 2, tg = lane & 3;
    const int wr = wid >> 2, wc = wid & 3;
    const int t = blockIdx.z;
    const int m0 = blockIdx.x * 128, n0 = blockIdx.y * 128;

    float acc[4][4][4];
#pragma unroll
    for (int i = 0; i < 4; i++)
#pragma unroll
        for (int j = 0; j < 4; j++)
#pragma unroll
            for (int q = 0; q < 4; q++) acc[i][j][q] = 0.f;

    const int lr = tid >> 1, half = tid & 1;     // load row / 16B-half
    const int gr = m0 + lr;                       // A global row
    const int nr = n0 + lr;                       // B global row (n index)

    auto loadTile = [&](int kt, int buf) {
        const int k0 = kt * 16;
        uint32_t sb = sbase + (uint32_t)buf * BUF_W * 4;
        uint32_t wo = (uint32_t)(lr * ROW_W + half * 4) * 4;
        int asz = gr < NN ? 16 : 0;
        cp16(sb + wo, g_xh + (size_t)gr * KD + k0 + half * 8, asz);
        size_t woff = ((size_t)t * KD + nr) * KD + k0 + half * 8;
        cp16(sb + PLANE_W * 4 + wo, g_Wh + woff, 16);
        asm volatile("cp.async.commit_group;" ::: "memory");
    };

    loadTile(0, 0);

    for (int kt = 0; kt < 16; kt++) {
        const int buf = kt & 1;
        if (kt < 15) loadTile(kt + 1, buf ^ 1);
        if (kt < 15) asm volatile("cp.async.wait_group 1;" ::: "memory");
        else         asm volatile("cp.async.wait_group 0;" ::: "memory");
        __syncthreads();

        const uint32_t* Ah = smw + buf * BUF_W;
        const uint32_t* Bh = Ah + PLANE_W;

        uint32_t ah[4][4];
#pragma unroll
        for (int mf = 0; mf < 4; mf++) {
            int w0 = (wr * 64 + mf * 16 + g) * ROW_W + tg;
            int w1 = w0 + 8 * ROW_W;
            ah[mf][0] = Ah[w0]; ah[mf][1] = Ah[w1];
            ah[mf][2] = Ah[w0 + 4]; ah[mf][3] = Ah[w1 + 4];
        }
#pragma unroll
        for (int nf = 0; nf < 4; nf++) {
            int nw = (wc * 32 + nf * 8 + g) * ROW_W + tg;
            uint32_t bh0 = Bh[nw], bh1 = Bh[nw + 4];
#pragma unroll
            for (int mf = 0; mf < 4; mf++)
                mma16(acc[mf][nf], ah[mf], bh0, bh1);
        }
        __syncthreads();
    }

    // ---- epilogue: store h (fp16), compute per-head attention scores (fp32) ----
    const int head = blockIdx.y * 4 + wc;
    float wl[4][2], wrt[4][2];
#pragma unroll
    for (int nf = 0; nf < 4; nf++) {
        int lc = nf * 8 + tg * 2;
        wl[nf][0]  = __ldg(a_l + ((size_t)t * HH + head) * HD + lc);
        wl[nf][1]  = __ldg(a_l + ((size_t)t * HH + head) * HD + lc + 1);
        wrt[nf][0] = __ldg(a_r + ((size_t)t * HH + head) * HD + lc);
        wrt[nf][1] = __ldg(a_r + ((size_t)t * HH + head) * HD + lc + 1);
    }
#pragma unroll
    for (int mf = 0; mf < 4; mf++) {
        int r0 = m0 + wr * 64 + mf * 16 + g;
        int r1 = r0 + 8;
        float dl0 = 0.f, dr0 = 0.f, dl1 = 0.f, dr1 = 0.f;
#pragma unroll
        for (int nf = 0; nf < 4; nf++) {
            int col = n0 + wc * 32 + nf * 8 + tg * 2;
            float c0 = acc[mf][nf][0], c1 = acc[mf][nf][1];
            float c2 = acc[mf][nf][2], c3 = acc[mf][nf][3];
            dl0 += c0 * wl[nf][0] + c1 * wl[nf][1];
            dr0 += c0 * wrt[nf][0] + c1 * wrt[nf][1];
            dl1 += c2 * wl[nf][0] + c3 * wl[nf][1];
            dr1 += c2 * wrt[nf][0] + c3 * wrt[nf][1];
            if (r0 < NN)
                *(__half2*)&g_h[((size_t)t * NN + r0) * KD + col] =
                    __floats2half2_rn(c0, c1);
            if (r1 < NN)
                *(__half2*)&g_h[((size_t)t * NN + r1) * KD + col] =
                    __floats2half2_rn(c2, c3);
        }
#pragma unroll
        for (int o = 1; o <= 2; o <<= 1) {
            dl0 += __shfl_xor_sync(0xffffffffu, dl0, o);
            dr0 += __shfl_xor_sync(0xffffffffu, dr0, o);
            dl1 += __shfl_xor_sync(0xffffffffu, dl1, o);
            dr1 += __shfl_xor_sync(0xffffffffu, dr1, o);
        }
        if (tg == 0) {
            if (r0 < NN) {
                g_sl[((size_t)t * NN + r0) * HH + head] = dl0;
                g_sr[((size_t)t * NN + r0) * HH + head] = dr0;
            }
            if (r1 < NN) {
                g_sl[((size_t)t * NN + r1) * HH + head] = dl1;
                g_sr[((size_t)t * NN + r1) * HH + head] = dr1;
            }
        }
    }
}

// ---------------- fused gather-aggregate + semantic attention ----------------
// One warp per dst node; fp16 h gather (16B/lane/edge); all state in registers.
__global__ void __launch_bounds__(256) agg_sem_kernel(const float* __restrict__ att_w,
                                                      const float* __restrict__ att_b,
                                                      float* __restrict__ out) {
    int n = (blockIdx.x * blockDim.x + threadIdx.x) >> 5;
    int lane = threadIdx.x & 31;
    if (n >= NN) return;
    int head = lane >> 2;

    float4 o0[TT], o1[TT];

#pragma unroll
    for (int t = 0; t < TT; t++) {
        float srv = g_sr[((size_t)t * NN + n) * HH + head];
        int cnt = g_cnt[t * NN + n];
        cnt = cnt < CAP ? cnt : CAP;
        const int* adj = g_adj + ((size_t)t * NN + n) * CAP;
        float4 a0 = make_float4(0.f, 0.f, 0.f, 0.f);
        float4 a1 = make_float4(0.f, 0.f, 0.f, 0.f);
        float den = 0.f;
        int e = 0;
        for (; e + 4 <= cnt; e += 4) {
            int4 s4 = *(const int4*)(adj + e);
            float sc0 = __ldg(g_sl + ((size_t)t * NN + s4.x) * HH + head) + srv;
            float sc1 = __ldg(g_sl + ((size_t)t * NN + s4.y) * HH + head) + srv;
            float sc2 = __ldg(g_sl + ((size_t)t * NN + s4.z) * HH + head) + srv;
            float sc3 = __ldg(g_sl + ((size_t)t * NN + s4.w) * HH + head) + srv;
            uint4 r0v = *(const uint4*)(g_h + ((size_t)t * NN + s4.x) * KD + lane * 8);
            uint4 r1v = *(const uint4*)(g_h + ((size_t)t * NN + s4.y) * KD + lane * 8);
            uint4 r2v = *(const uint4*)(g_h + ((size_t)t * NN + s4.z) * KD + lane * 8);
            uint4 r3v = *(const uint4*)(g_h + ((size_t)t * NN + s4.w) * KD + lane * 8);
            sc0 = sc0 > 0.f ? sc0 : 0.2f * sc0;
            sc1 = sc1 > 0.f ? sc1 : 0.2f * sc1;
            sc2 = sc2 > 0.f ? sc2 : 0.2f * sc2;
            sc3 = sc3 > 0.f ? sc3 : 0.2f * sc3;
            float x0 = __expf(sc0), x1 = __expf(sc1), x2 = __expf(sc2), x3 = __expf(sc3);
            den += (x0 + x1) + (x2 + x3);
            const __half2* h0 = (const __half2*)&r0v;
            const __half2* h1 = (const __half2*)&r1v;
            const __half2* h2 = (const __half2*)&r2v;
            const __half2* h3 = (const __half2*)&r3v;
            float2 f;
            f = __half22float2(h0[0]); a0.x += x0 * f.x; a0.y += x0 * f.y;
            f = __half22float2(h0[1]); a0.z += x0 * f.x; a0.w += x0 * f.y;
            f = __half22float2(h0[2]); a1.x += x0 * f.x; a1.y += x0 * f.y;
            f = __half22float2(h0[3]); a1.z += x0 * f.x; a1.w += x0 * f.y;
            f = __half22float2(h1[0]); a0.x += x1 * f.x; a0.y += x1 * f.y;
            f = __half22float2(h1[1]); a0.z += x1 * f.x; a0.w += x1 * f.y;
            f = __half22float2(h1[2]); a1.x += x1 * f.x; a1.y += x1 * f.y;
            f = __half22float2(h1[3]); a1.z += x1 * f.x; a1.w += x1 * f.y;
            f = __half22float2(h2[0]); a0.x += x2 * f.x; a0.y += x2 * f.y;
            f = __half22float2(h2[1]); a0.z += x2 * f.x; a0.w += x2 * f.y;
            f = __half22float2(h2[2]); a1.x += x2 * f.x; a1.y += x2 * f.y;
            f = __half22float2(h2[3]); a1.z += x2 * f.x; a1.w += x2 * f.y;
            f = __half22float2(h3[0]); a0.x += x3 * f.x; a0.y += x3 * f.y;
            f = __half22float2(h3[1]); a0.z += x3 * f.x; a0.w += x3 * f.y;
            f = __half22float2(h3[2]); a1.x += x3 * f.x; a1.y += x3 * f.y;
            f = __half22float2(h3[3]); a1.z += x3 * f.x; a1.w += x3 * f.y;
        }
        for (; e < cnt; e++) {
            int s0 = __ldg(adj + e);
            float sc0 = __ldg(g_sl + ((size_t)t * NN + s0) * HH + head) + srv;
            uint4 rv = *(const uint4*)(g_h + ((size_t)t * NN + s0) * KD + lane * 8);
            sc0 = sc0 > 0.f ? sc0 : 0.2f * sc0;
            float x0 = __expf(sc0);
            den += x0;
            const __half2* hp = (const __half2*)&rv;
            float2 f;
            f = __half22float2(hp[0]); a0.x += x0 * f.x; a0.y += x0 * f.y;
            f = __half22float2(hp[1]); a0.z += x0 * f.x; a0.w += x0 * f.y;
            f = __half22float2(hp[2]); a1.x += x0 * f.x; a1.y += x0 * f.y;
            f = __half22float2(hp[3]); a1.z += x0 * f.x; a1.w += x0 * f.y;
        }
        float inv = den > 0.f ? __frcp_rn(den) : 1.f;
        o0[t] = make_float4(a0.x * inv, a0.y * inv, a0.z * inv, a0.w * inv);
        o1[t] = make_float4(a1.x * inv, a1.y * inv, a1.z * inv, a1.w * inv);
    }

    // semantic attention
    float4 w0 = ((const float4*)att_w)[lane * 2];
    float4 w1 = ((const float4*)att_w)[lane * 2 + 1];
    float b = att_b[0];
    float4 acc0 = make_float4(0.f, 0.f, 0.f, 0.f);
    float4 acc1 = make_float4(0.f, 0.f, 0.f, 0.f);
#pragma unroll
    for (int t = 0; t < TT; t++) {
        float p = o0[t].x * w0.x + o0[t].y * w0.y + o0[t].z * w0.z + o0[t].w * w0.w
                + o1[t].x * w1.x + o1[t].y * w1.y + o1[t].z * w1.z + o1[t].w * w1.w;
#pragma unroll
        for (int o = 16; o; o >>= 1) p += __shfl_xor_sync(0xffffffffu, p, o);
        float att = p + b;
        acc0.x += att * o0[t].x; acc0.y += att * o0[t].y;
        acc0.z += att * o0[t].z; acc0.w += att * o0[t].w;
        acc1.x += att * o1[t].x; acc1.y += att * o1[t].y;
        acc1.z += att * o1[t].z; acc1.w += att * o1[t].w;
    }
    float4* dp = (float4*)(out + (size_t)n * KD + lane * 8);
    dp[0] = acc0;
    dp[1] = acc1;
}

extern "C" void kernel_launch(void* const* d_in, const int* in_sizes, int n_in,
                              void* d_out, int out_size) {
    const float* x     = (const float*)d_in[0];
    const int*   ei    = (const int*)d_in[1];
    const float* W     = (const float*)d_in[2];
    const float* a_l   = (const float*)d_in[3];
    const float* a_r   = (const float*)d_in[4];
    const float* att_w = (const float*)d_in[5];
    const float* att_b = (const float*)d_in[6];
    float* out = (float*)d_out;

    static int smem_set = 0;
    if (!smem_set) {
        cudaFuncSetAttribute(gemm_scores_kernel,
                             cudaFuncAttributeMaxDynamicSharedMemorySize, SM_TOTAL);
        smem_set = 1;
    }

    zero_cnt_kernel<<<(TT * NN + 255) / 256, 256>>>();
    build_kernel<<<(TT * EE + 255) / 256, 256>>>(ei);
    convert_kernel<<<(NN * KD + TT * KD * KD + 255) / 256, 256>>>(x, W);

    dim3 ggrid((NN + 127) / 128, 2, TT);
    gemm_scores_kernel<<<ggrid, 256, SM_TOTAL>>>(a_l, a_r);

    agg_sem_kernel<<<(NN * 32 + 255) / 256, 256>>>(att_w, att_b, out);
}